// round 13
// baseline (speedup 1.0000x reference)
#include <cuda_runtime.h>
#include <cuda_fp16.h>
#include <math.h>
#include <stdint.h>

#define TOK 16384
#define HDIM 1024
#define DFF  4096

// ---------------- scratch (static device globals; no allocation) ----------------
__device__ __align__(256) __half g_X  [(size_t)TOK * HDIM];   // compact xg fp16
__device__ __align__(256) __half g_A  [(size_t)TOK * DFF];    // compact relu intermediate
__device__ __align__(256) __half g_W1H[(size_t)HDIM * DFF];   // W1 fp16 [K,N]
__device__ __align__(256) __half g_W2H[(size_t)DFF * HDIM];   // W2 fp16 [K,N]
__device__ int g_rowmap[TOK];
__device__ int g_count;
__device__ int g_lab64;

// ---------------- kernel A: both weight casts + labels detect + counter reset ----
__global__ void prep_kernel(const float* __restrict__ W1, const float* __restrict__ W2,
                            __half* __restrict__ o1, __half* __restrict__ o2,
                            int n4each, const int* __restrict__ lab) {
    if (blockIdx.x == 0) {
        __shared__ int bad;
        if (threadIdx.x == 0) { bad = 0; g_count = 0; }
        __syncthreads();
        int local = 0;
        // int64 labels: (lo,hi) pairs with hi in {0,-1}, hi==-1 <=> lo==-100.
        for (int i = threadIdx.x; i < 2048; i += blockDim.x) {
            int lo = lab[2 * i], hi = lab[2 * i + 1];
            bool ok64 = (hi == 0 && lo >= 0) || (hi == -1 && lo == -100);
            if (!ok64) local = 1;
        }
        if (local) bad = 1;
        __syncthreads();
        if (threadIdx.x == 0) g_lab64 = bad ? 0 : 1;
    }
    int i = blockIdx.x * blockDim.x + threadIdx.x;
    const float4* src;
    uint2* dst;
    int j;
    if (i < n4each)      { src = (const float4*)W1; dst = (uint2*)o1; j = i; }
    else                 { src = (const float4*)W2; dst = (uint2*)o2; j = i - n4each;
                           if (j >= n4each) return; }
    float4 v = src[j];
    __half2 h0 = __floats2half2_rn(v.x, v.y);
    __half2 h1 = __floats2half2_rn(v.z, v.w);
    uint2 r;
    r.x = *(uint32_t*)&h0;
    r.y = *(uint32_t*)&h1;
    dst[j] = r;
}

// ---------------- kernel B: gate + compact gather + zero dropped rows ------------
__global__ void gate_kernel(const float* __restrict__ hs,
                            const float* __restrict__ Wg,
                            const float* __restrict__ bg,
                            const void*  __restrict__ labels,
                            float* __restrict__ out) {
    __shared__ float4 sWg[HDIM / 4];
    for (int i = threadIdx.x; i < HDIM / 4; i += blockDim.x)
        sWg[i] = ((const float4*)Wg)[i];
    __syncthreads();
    int warp = threadIdx.x >> 5, lane = threadIdx.x & 31;
    int t = blockIdx.x * 8 + warp;
    const float4* hr = (const float4*)(hs + (size_t)t * HDIM);
    float4 v[8];
    float s = 0.f;
#pragma unroll
    for (int i = 0; i < 8; i++) {
        v[i] = hr[lane + 32 * i];
        float4 w4 = sWg[lane + 32 * i];
        s += v[i].x * w4.x + v[i].y * w4.y + v[i].z * w4.z + v[i].w * w4.w;
    }
#pragma unroll
    for (int o = 16; o; o >>= 1) s += __shfl_xor_sync(0xffffffffu, s, o);
    float logit = s + bg[0];
    float w = 1.f / (1.f + expf(-logit));
    long long lab;
    if (g_lab64) lab = ((const long long*)labels)[t];
    else         lab = (long long)(((const int*)labels)[t]);
    bool keep = (logit >= 0.f) || (lab == -100LL);
    int slot = -1;
    if (lane == 0 && keep) slot = atomicAdd(&g_count, 1);
    slot = __shfl_sync(0xffffffffu, slot, 0);
    if (keep) {
        if (lane == 0) g_rowmap[slot] = t;
        uint2* xr = (uint2*)(g_X + (size_t)slot * HDIM);
#pragma unroll
        for (int i = 0; i < 8; i++) {
            __half2 h0 = __floats2half2_rn(v[i].x * w, v[i].y * w);
            __half2 h1 = __floats2half2_rn(v[i].z * w, v[i].w * w);
            uint2 r;
            r.x = *(uint32_t*)&h0;
            r.y = *(uint32_t*)&h1;
            xr[lane + 32 * i] = r;
        }
    } else {
        float4 z = make_float4(0.f, 0.f, 0.f, 0.f);
        float4* orow = (float4*)(out + (size_t)t * HDIM);
#pragma unroll
        for (int i = 0; i < 8; i++) orow[lane + 32 * i] = z;
    }
}

// ---------------- GEMM: C[Mc,N] = A[Mc,K] * B[K,N]  (B native [K,N]) ------------
// CTA tile 128x256, 512 threads (16 warps, 4x4), warp tile 32x64, BK=64, 3 stages.
// Next-stage cp.async interleaved between kk-chunks (R9 pattern).
#define BM 128
#define BN 256
#define BK 64
#define STAGES 3
#define NTHREADS 512
#define A_PITCH 144                       // (64+8) halves * 2B
#define B_PITCH 528                       // (256+8) halves * 2B
#define STAGE_A (BM * A_PITCH)            // 18432
#define STAGE_B (BK * B_PITCH)            // 33792
#define STAGE_BYTES (STAGE_A + STAGE_B)   // 52224
#define SMEM_BYTES (STAGES * STAGE_BYTES) // 156672

__device__ __forceinline__ uint32_t smem_u32(const void* p) {
    uint32_t a;
    asm("{ .reg .u64 t; cvta.to.shared.u64 t, %1; cvt.u32.u64 %0, t; }" : "=r"(a) : "l"(p));
    return a;
}
__device__ __forceinline__ void cp16s(uint32_t s, const void* g) {
    asm volatile("cp.async.cg.shared.global [%0], [%1], 16;\n" :: "r"(s), "l"(g));
}
__device__ __forceinline__ void cp16z(uint32_t s, const void* g, int valid) {
    int sz = valid ? 16 : 0;
    asm volatile("cp.async.cg.shared.global [%0], [%1], 16, %2;\n" :: "r"(s), "l"(g), "r"(sz));
}
__device__ __forceinline__ void cp_commit() { asm volatile("cp.async.commit_group;\n"); }
template <int N_> __device__ __forceinline__ void cp_wait() {
    asm volatile("cp.async.wait_group %0;\n" :: "n"(N_));
}
__device__ __forceinline__ void ldm_x4(uint32_t a, uint32_t& r0, uint32_t& r1,
                                       uint32_t& r2, uint32_t& r3) {
    asm volatile("ldmatrix.sync.aligned.m8n8.x4.shared.b16 {%0,%1,%2,%3}, [%4];"
                 : "=r"(r0), "=r"(r1), "=r"(r2), "=r"(r3) : "r"(a));
}
__device__ __forceinline__ void ldm_x4t(uint32_t a, uint32_t& r0, uint32_t& r1,
                                        uint32_t& r2, uint32_t& r3) {
    asm volatile("ldmatrix.sync.aligned.m8n8.x4.trans.shared.b16 {%0,%1,%2,%3}, [%4];"
                 : "=r"(r0), "=r"(r1), "=r"(r2), "=r"(r3) : "r"(a));
}

__device__ __forceinline__ void load_stage_A(uint32_t base,
                                             const __half* __restrict__ A,
                                             int K, int bm, int k0, int tid, int Mc) {
#pragma unroll
    for (int i = 0; i < 2; i++) {           // A: 128 rows x 8 chunks = 1024
        int idx = tid + i * NTHREADS;
        int row = idx >> 3, cc = idx & 7;
        int gr = bm + row;
        cp16z(base + row * A_PITCH + cc * 16, A + (size_t)gr * K + k0 + cc * 8, gr < Mc);
    }
}
template <int HALF>
__device__ __forceinline__ void load_stage_B(uint32_t base,
                                             const __half* __restrict__ B,
                                             int N, int bn, int k0, int tid) {
    uint32_t bb = base + STAGE_A;
#pragma unroll
    for (int i = HALF * 2; i < HALF * 2 + 2; i++) {  // B: 64 rows x 32 chunks = 2048
        int idx = tid + i * NTHREADS;
        int row = idx >> 5, cc = idx & 31;
        cp16s(bb + row * B_PITCH + cc * 16, B + (size_t)(k0 + row) * N + bn + cc * 8);
    }
}

// mode 0: g_A[row] = relu(acc+bias) fp16 ; mode 1: d_out[rowmap[row]] = acc+bias fp32
__global__ void __launch_bounds__(NTHREADS) hgemm_kernel(
    const __half* __restrict__ A, const __half* __restrict__ B,
    const float* __restrict__ bias, void* __restrict__ Cout,
    int N, int K, int mode)
{
    int Mc = *(volatile int*)&g_count;
    int bm = blockIdx.y * BM;
    if (bm >= Mc) return;
    int bn = blockIdx.x * BN;

    extern __shared__ char smraw[];
    uint32_t sb = smem_u32(smraw);
    int tid = threadIdx.x;
    int warp = tid >> 5, lane = tid & 31;
    int wm = warp & 3, wn = warp >> 2;             // 4x4 warps; warp tile 32x64

    float acc[2][8][4];
#pragma unroll
    for (int i = 0; i < 2; i++)
#pragma unroll
        for (int j = 0; j < 8; j++)
#pragma unroll
            for (int r = 0; r < 4; r++) acc[i][j][r] = 0.f;

    int kt = K / BK;
#pragma unroll
    for (int s = 0; s < STAGES - 1; s++) {
        load_stage_A(sb + s * STAGE_BYTES, A, K, bm, s * BK, tid, Mc);
        load_stage_B<0>(sb + s * STAGE_BYTES, B, N, bn, s * BK, tid);
        load_stage_B<1>(sb + s * STAGE_BYTES, B, N, bn, s * BK, tid);
        cp_commit();
    }

    uint32_t a_lane = (uint32_t)(wm * 32 + (lane & 15)) * A_PITCH + (((lane >> 4) << 3) << 1);
    uint32_t b_lane = (uint32_t)((lane & 7) + (((lane >> 3) & 1) << 3)) * B_PITCH
                    + (((uint32_t)(wn * 64 + ((lane >> 4) << 3))) << 1);
    int g = lane >> 2, tq = lane & 3;

    for (int k = 0; k < kt; k++) {
        cp_wait<STAGES - 2>();
        __syncthreads();
        int kn = k + STAGES - 1;
        int do_load = kn < kt;
        uint32_t lbase = sb + (kn % STAGES) * STAGE_BYTES;
        int lk0 = kn * BK;
        uint32_t a_base = sb + (k % STAGES) * STAGE_BYTES + a_lane;
        uint32_t b_base = sb + (k % STAGES) * STAGE_BYTES + STAGE_A + b_lane;
#pragma unroll
        for (int kk = 0; kk < 4; kk++) {
            uint32_t afr[2][4], bfr[8][2];
#pragma unroll
            for (int mi = 0; mi < 2; mi++)
                ldm_x4(a_base + mi * (16 * A_PITCH) + kk * 32,
                       afr[mi][0], afr[mi][1], afr[mi][2], afr[mi][3]);
#pragma unroll
            for (int p = 0; p < 4; p++)
                ldm_x4t(b_base + kk * (16 * B_PITCH) + p * 32,
                        bfr[2 * p][0], bfr[2 * p][1], bfr[2 * p + 1][0], bfr[2 * p + 1][1]);
#pragma unroll
            for (int mi = 0; mi < 2; mi++)
#pragma unroll
                for (int ni = 0; ni < 8; ni++)
                    asm volatile(
                        "mma.sync.aligned.m16n8k16.row.col.f32.f16.f16.f32 "
                        "{%0,%1,%2,%3}, {%4,%5,%6,%7}, {%8,%9}, {%0,%1,%2,%3};\n"
                        : "+f"(acc[mi][ni][0]), "+f"(acc[mi][ni][1]),
                          "+f"(acc[mi][ni][2]), "+f"(acc[mi][ni][3])
                        : "r"(afr[mi][0]), "r"(afr[mi][1]),
                          "r"(afr[mi][2]), "r"(afr[mi][3]),
                          "r"(bfr[ni][0]), "r"(bfr[ni][1]));
            if (kk == 0 && do_load) load_stage_A(lbase, A, K, bm, lk0, tid, Mc);
            if (kk == 1 && do_load) load_stage_B<0>(lbase, B, N, bn, lk0, tid);
            if (kk == 2) {
                if (do_load) load_stage_B<1>(lbase, B, N, bn, lk0, tid);
                cp_commit();
            }
        }
    }

    int r0 = bm + wm * 32;
    int c0 = bn + wn * 64;
    if (mode == 0) {
        __half* C = (__half*)Cout;
#pragma unroll
        for (int mi = 0; mi < 2; mi++) {
            int row = r0 + mi * 16 + g;
#pragma unroll
            for (int ni = 0; ni < 8; ni++) {
                int col = c0 + ni * 8 + tq * 2;
                float2 bb = *(const float2*)(bias + col);
                float v0 = fmaxf(acc[mi][ni][0] + bb.x, 0.f);
                float v1 = fmaxf(acc[mi][ni][1] + bb.y, 0.f);
                float v2 = fmaxf(acc[mi][ni][2] + bb.x, 0.f);
                float v3 = fmaxf(acc[mi][ni][3] + bb.y, 0.f);
                *(__half2*)(C + (size_t)row * N + col)       = __floats2half2_rn(v0, v1);
                *(__half2*)(C + (size_t)(row + 8) * N + col) = __floats2half2_rn(v2, v3);
            }
        }
    } else {
        float* C = (float*)Cout;
#pragma unroll
        for (int mi = 0; mi < 2; mi++) {
            int row = r0 + mi * 16 + g;
            int ok0 = row < Mc, ok1 = (row + 8) < Mc;
            size_t t0 = ok0 ? (size_t)g_rowmap[row] : 0;
            size_t t1 = ok1 ? (size_t)g_rowmap[row + 8] : 0;
#pragma unroll
            for (int ni = 0; ni < 8; ni++) {
                int col = c0 + ni * 8 + tq * 2;
                float2 bb = *(const float2*)(bias + col);
                if (ok0)
                    *(float2*)(C + t0 * N + col) =
                        make_float2(acc[mi][ni][0] + bb.x, acc[mi][ni][1] + bb.y);
                if (ok1)
                    *(float2*)(C + t1 * N + col) =
                        make_float2(acc[mi][ni][2] + bb.x, acc[mi][ni][3] + bb.y);
            }
        }
    }
}

// ---------------- host launcher --------------------------------------------------
extern "C" void kernel_launch(void* const* d_in, const int* in_sizes, int n_in,
                              void* d_out, int out_size) {
    const float* hs = (const float*)d_in[0];
    const float* Wg = (const float*)d_in[3];
    const float* bg = (const float*)d_in[4];
    const float* W1 = (const float*)d_in[5];
    const float* b1 = (const float*)d_in[6];
    const float* W2 = (const float*)d_in[7];
    const float* b2 = (const float*)d_in[8];
    const void*  labels = d_in[9];

    void *pX, *pA, *pW1H, *pW2H;
    cudaGetSymbolAddress(&pX, g_X);
    cudaGetSymbolAddress(&pA, g_A);
    cudaGetSymbolAddress(&pW1H, g_W1H);
    cudaGetSymbolAddress(&pW2H, g_W2H);

    cudaFuncSetAttribute(hgemm_kernel, cudaFuncAttributeMaxDynamicSharedMemorySize, SMEM_BYTES);
    int n4 = HDIM * DFF / 4;

    // prep: both weight casts + labels-dtype detect + counter reset (one launch)
    prep_kernel<<<(2 * n4 + 255) / 256, 256>>>(W1, W2, (__half*)pW1H, (__half*)pW2H,
                                               n4, (const int*)labels);
    gate_kernel<<<TOK / 8, 256>>>(hs, Wg, bg, labels, (float*)d_out);
    // GEMM1: g_A = relu(Xc @ W1 + b1), fp16 (compact rows)
    hgemm_kernel<<<dim3(DFF / BN, TOK / BM), NTHREADS, SMEM_BYTES>>>(
        (const __half*)pX, (const __half*)pW1H, b1, pA, DFF, HDIM, 0);
    // GEMM2: d_out[rowmap] = Ac @ W2 + b2, fp32 scatter
    hgemm_kernel<<<dim3(HDIM / BN, TOK / BM), NTHREADS, SMEM_BYTES>>>(
        (const __half*)pA, (const __half*)pW2H, b2, d_out, HDIM, DFF, 1);
}

// round 14
// speedup vs baseline: 1.1402x; 1.1402x over previous
#include <cuda_runtime.h>
#include <cuda_fp16.h>
#include <math.h>
#include <stdint.h>

#define TOK 16384
#define HDIM 1024
#define DFF  4096

// ---------------- scratch (static device globals; no allocation) ----------------
__device__ __align__(256) __half g_X  [(size_t)TOK * HDIM];   // compact xg fp16
__device__ __align__(256) __half g_A  [(size_t)TOK * DFF];    // compact relu intermediate
__device__ __align__(256) __half g_W1H[(size_t)HDIM * DFF];   // W1 fp16 [K,N]
__device__ __align__(256) __half g_W2H[(size_t)DFF * HDIM];   // W2 fp16 [K,N]
__device__ int g_rowmap[TOK];
__device__ int g_count;
__device__ int g_lab64;

// ---------------- kernel A: W1 cast + labels-dtype detect + counter reset --------
__global__ void prep_kernel(const float* __restrict__ in, __half* __restrict__ out,
                            int n4, const int* __restrict__ lab) {
    if (blockIdx.x == 0) {
        __shared__ int bad;
        if (threadIdx.x == 0) { bad = 0; g_count = 0; }
        __syncthreads();
        int local = 0;
        // int64 labels: (lo,hi) pairs with hi in {0,-1}, hi==-1 <=> lo==-100.
        for (int i = threadIdx.x; i < 2048; i += blockDim.x) {
            int lo = lab[2 * i], hi = lab[2 * i + 1];
            bool ok64 = (hi == 0 && lo >= 0) || (hi == -1 && lo == -100);
            if (!ok64) local = 1;
        }
        if (local) bad = 1;
        __syncthreads();
        if (threadIdx.x == 0) g_lab64 = bad ? 0 : 1;
    }
    int i = blockIdx.x * blockDim.x + threadIdx.x;
    if (i >= n4) return;
    float4 v = ((const float4*)in)[i];
    __half2 h0 = __floats2half2_rn(v.x, v.y);
    __half2 h1 = __floats2half2_rn(v.z, v.w);
    uint2 r;
    r.x = *(uint32_t*)&h0;
    r.y = *(uint32_t*)&h1;
    ((uint2*)out)[i] = r;
}

// ---------------- kernel B: gate + compact gather + zero dropped rows ------------
__global__ void gate_kernel(const float* __restrict__ hs,
                            const float* __restrict__ Wg,
                            const float* __restrict__ bg,
                            const void*  __restrict__ labels,
                            float* __restrict__ out) {
    __shared__ float4 sWg[HDIM / 4];
    for (int i = threadIdx.x; i < HDIM / 4; i += blockDim.x)
        sWg[i] = ((const float4*)Wg)[i];
    __syncthreads();
    int warp = threadIdx.x >> 5, lane = threadIdx.x & 31;
    int t = blockIdx.x * 8 + warp;
    const float4* hr = (const float4*)(hs + (size_t)t * HDIM);
    float4 v[8];
    float s = 0.f;
#pragma unroll
    for (int i = 0; i < 8; i++) {
        v[i] = hr[lane + 32 * i];
        float4 w4 = sWg[lane + 32 * i];
        s += v[i].x * w4.x + v[i].y * w4.y + v[i].z * w4.z + v[i].w * w4.w;
    }
#pragma unroll
    for (int o = 16; o; o >>= 1) s += __shfl_xor_sync(0xffffffffu, s, o);
    float logit = s + bg[0];
    float w = 1.f / (1.f + expf(-logit));
    long long lab;
    if (g_lab64) lab = ((const long long*)labels)[t];
    else         lab = (long long)(((const int*)labels)[t]);
    bool keep = (logit >= 0.f) || (lab == -100LL);
    int slot = -1;
    if (lane == 0 && keep) slot = atomicAdd(&g_count, 1);
    slot = __shfl_sync(0xffffffffu, slot, 0);
    if (keep) {
        if (lane == 0) g_rowmap[slot] = t;
        uint2* xr = (uint2*)(g_X + (size_t)slot * HDIM);
#pragma unroll
        for (int i = 0; i < 8; i++) {
            __half2 h0 = __floats2half2_rn(v[i].x * w, v[i].y * w);
            __half2 h1 = __floats2half2_rn(v[i].z * w, v[i].w * w);
            uint2 r;
            r.x = *(uint32_t*)&h0;
            r.y = *(uint32_t*)&h1;
            xr[lane + 32 * i] = r;
        }
    } else {
        float4 z = make_float4(0.f, 0.f, 0.f, 0.f);
        float4* orow = (float4*)(out + (size_t)t * HDIM);
#pragma unroll
        for (int i = 0; i < 8; i++) orow[lane + 32 * i] = z;
    }
}

// ---------------- kernel C: plain fp32 -> fp16 cast (W2) -------------------------
__global__ void cast_kernel(const float* __restrict__ in, __half* __restrict__ out,
                            int n4) {
    int i = blockIdx.x * blockDim.x + threadIdx.x;
    if (i >= n4) return;
    float4 v = ((const float4*)in)[i];
    __half2 h0 = __floats2half2_rn(v.x, v.y);
    __half2 h1 = __floats2half2_rn(v.z, v.w);
    uint2 r;
    r.x = *(uint32_t*)&h0;
    r.y = *(uint32_t*)&h1;
    ((uint2*)out)[i] = r;
}

// ---------------- GEMM: C[Mc,N] = A[Mc,K] * B[K,N]  (B native [K,N]) ------------
// CTA tile 128x128, 256 threads (8 warps, 4x2), warp tile 32x64, BK=64, 3 stages.
// Next-stage cp.async interleaved between kk-chunks. MODE/N/K compile-time.
#define BM 128
#define BN 128
#define BK 64
#define STAGES 3
#define NTHREADS 256
#define A_PITCH 144                       // (64+8) halves * 2B
#define B_PITCH 272                       // (128+8) halves * 2B
#define STAGE_A (BM * A_PITCH)            // 18432
#define STAGE_B (BK * B_PITCH)            // 17408
#define STAGE_BYTES (STAGE_A + STAGE_B)   // 35840
#define SMEM_BYTES (STAGES * STAGE_BYTES) // 107520

__device__ __forceinline__ uint32_t smem_u32(const void* p) {
    uint32_t a;
    asm("{ .reg .u64 t; cvta.to.shared.u64 t, %1; cvt.u32.u64 %0, t; }" : "=r"(a) : "l"(p));
    return a;
}
__device__ __forceinline__ void cp16s(uint32_t s, const void* g) {
    asm volatile("cp.async.cg.shared.global [%0], [%1], 16;\n" :: "r"(s), "l"(g));
}
__device__ __forceinline__ void cp16z(uint32_t s, const void* g, int valid) {
    int sz = valid ? 16 : 0;
    asm volatile("cp.async.cg.shared.global [%0], [%1], 16, %2;\n" :: "r"(s), "l"(g), "r"(sz));
}
__device__ __forceinline__ void cp_commit() { asm volatile("cp.async.commit_group;\n"); }
template <int N_> __device__ __forceinline__ void cp_wait() {
    asm volatile("cp.async.wait_group %0;\n" :: "n"(N_));
}
__device__ __forceinline__ void ldm_x4(uint32_t a, uint32_t& r0, uint32_t& r1,
                                       uint32_t& r2, uint32_t& r3) {
    asm volatile("ldmatrix.sync.aligned.m8n8.x4.shared.b16 {%0,%1,%2,%3}, [%4];"
                 : "=r"(r0), "=r"(r1), "=r"(r2), "=r"(r3) : "r"(a));
}
__device__ __forceinline__ void ldm_x4t(uint32_t a, uint32_t& r0, uint32_t& r1,
                                        uint32_t& r2, uint32_t& r3) {
    asm volatile("ldmatrix.sync.aligned.m8n8.x4.trans.shared.b16 {%0,%1,%2,%3}, [%4];"
                 : "=r"(r0), "=r"(r1), "=r"(r2), "=r"(r3) : "r"(a));
}

template <int K>
__device__ __forceinline__ void load_stage_A(uint32_t base,
                                             const __half* __restrict__ A,
                                             int bm, int k0, int tid, int Mc) {
#pragma unroll
    for (int i = 0; i < 4; i++) {
        int idx = tid + i * NTHREADS;
        int row = idx >> 3, cc = idx & 7;
        int gr = bm + row;
        cp16z(base + row * A_PITCH + cc * 16, A + (size_t)gr * K + k0 + cc * 8, gr < Mc);
    }
}
template <int N>
__device__ __forceinline__ void load_stage_B(uint32_t base,
                                             const __half* __restrict__ B,
                                             int bn, int k0, int tid) {
    uint32_t bb = base + STAGE_A;
#pragma unroll
    for (int i = 0; i < 4; i++) {
        int idx = tid + i * NTHREADS;
        int row = idx >> 4, cc = idx & 15;
        cp16s(bb + row * B_PITCH + cc * 16, B + (size_t)(k0 + row) * N + bn + cc * 8);
    }
}

// MODE 0: g_A[row] = relu(acc+bias) fp16 ; MODE 1: d_out[rowmap[row]] = acc+bias fp32
template <int MODE, int N, int K>
__global__ void __launch_bounds__(NTHREADS) hgemm_kernel(
    const __half* __restrict__ A, const __half* __restrict__ B,
    const float* __restrict__ bias, void* __restrict__ Cout)
{
    int Mc = *(volatile int*)&g_count;
    int bm = blockIdx.y * BM;
    if (bm >= Mc) return;
    int bn = blockIdx.x * BN;

    extern __shared__ char smraw[];
    uint32_t sb = smem_u32(smraw);
    int tid = threadIdx.x;
    int warp = tid >> 5, lane = tid & 31;
    int wm = warp & 3, wn = warp >> 2;             // 4x2 warps; warp tile 32x64

    float acc[2][8][4];
#pragma unroll
    for (int i = 0; i < 2; i++)
#pragma unroll
        for (int j = 0; j < 8; j++)
#pragma unroll
            for (int r = 0; r < 4; r++) acc[i][j][r] = 0.f;

    constexpr int kt = K / BK;
#pragma unroll
    for (int s = 0; s < STAGES - 1; s++) {
        load_stage_A<K>(sb + s * STAGE_BYTES, A, bm, s * BK, tid, Mc);
        load_stage_B<N>(sb + s * STAGE_BYTES, B, bn, s * BK, tid);
        cp_commit();
    }

    uint32_t a_lane = (uint32_t)(wm * 32 + (lane & 15)) * A_PITCH + (((lane >> 4) << 3) << 1);
    uint32_t b_lane = (uint32_t)((lane & 7) + (((lane >> 3) & 1) << 3)) * B_PITCH
                    + (((uint32_t)(wn * 64 + ((lane >> 4) << 3))) << 1);
    int g = lane >> 2, tq = lane & 3;

#pragma unroll 1
    for (int k = 0; k < kt; k++) {
        cp_wait<STAGES - 2>();
        __syncthreads();
        int kn = k + STAGES - 1;
        int do_load = kn < kt;
        uint32_t lbase = sb + (kn % STAGES) * STAGE_BYTES;
        int lk0 = kn * BK;
        uint32_t a_base = sb + (k % STAGES) * STAGE_BYTES + a_lane;
        uint32_t b_base = sb + (k % STAGES) * STAGE_BYTES + STAGE_A + b_lane;
#pragma unroll
        for (int kk = 0; kk < 4; kk++) {
            uint32_t afr[2][4], bfr[8][2];
#pragma unroll
            for (int mi = 0; mi < 2; mi++)
                ldm_x4(a_base + mi * (16 * A_PITCH) + kk * 32,
                       afr[mi][0], afr[mi][1], afr[mi][2], afr[mi][3]);
#pragma unroll
            for (int p = 0; p < 4; p++)
                ldm_x4t(b_base + kk * (16 * B_PITCH) + p * 32,
                        bfr[2 * p][0], bfr[2 * p][1], bfr[2 * p + 1][0], bfr[2 * p + 1][1]);
#pragma unroll
            for (int mi = 0; mi < 2; mi++)
#pragma unroll
                for (int ni = 0; ni < 8; ni++)
                    asm volatile(
                        "mma.sync.aligned.m16n8k16.row.col.f32.f16.f16.f32 "
                        "{%0,%1,%2,%3}, {%4,%5,%6,%7}, {%8,%9}, {%0,%1,%2,%3};\n"
                        : "+f"(acc[mi][ni][0]), "+f"(acc[mi][ni][1]),
                          "+f"(acc[mi][ni][2]), "+f"(acc[mi][ni][3])
                        : "r"(afr[mi][0]), "r"(afr[mi][1]),
                          "r"(afr[mi][2]), "r"(afr[mi][3]),
                          "r"(bfr[ni][0]), "r"(bfr[ni][1]));
            if (kk == 0 && do_load) load_stage_A<K>(lbase, A, bm, lk0, tid, Mc);
            if (kk == 1) {
                if (do_load) load_stage_B<N>(lbase, B, bn, lk0, tid);
                cp_commit();
            }
        }
    }

    int r0 = bm + wm * 32;
    int c0 = bn + wn * 64;
    if (MODE == 0) {
        __half* C = (__half*)Cout;
#pragma unroll
        for (int mi = 0; mi < 2; mi++) {
            int row = r0 + mi * 16 + g;
#pragma unroll
            for (int ni = 0; ni < 8; ni++) {
                int col = c0 + ni * 8 + tq * 2;
                float2 bb = *(const float2*)(bias + col);
                float v0 = fmaxf(acc[mi][ni][0] + bb.x, 0.f);
                float v1 = fmaxf(acc[mi][ni][1] + bb.y, 0.f);
                float v2 = fmaxf(acc[mi][ni][2] + bb.x, 0.f);
                float v3 = fmaxf(acc[mi][ni][3] + bb.y, 0.f);
                *(__half2*)(C + (size_t)row * N + col)       = __floats2half2_rn(v0, v1);
                *(__half2*)(C + (size_t)(row + 8) * N + col) = __floats2half2_rn(v2, v3);
            }
        }
    } else {
        float* C = (float*)Cout;
#pragma unroll
        for (int mi = 0; mi < 2; mi++) {
            int row = r0 + mi * 16 + g;
            int ok0 = row < Mc, ok1 = (row + 8) < Mc;
            size_t t0 = ok0 ? (size_t)g_rowmap[row] : 0;
            size_t t1 = ok1 ? (size_t)g_rowmap[row + 8] : 0;
#pragma unroll
            for (int ni = 0; ni < 8; ni++) {
                int col = c0 + ni * 8 + tq * 2;
                float2 bb = *(const float2*)(bias + col);
                if (ok0)
                    *(float2*)(C + t0 * N + col) =
                        make_float2(acc[mi][ni][0] + bb.x, acc[mi][ni][1] + bb.y);
                if (ok1)
                    *(float2*)(C + t1 * N + col) =
                        make_float2(acc[mi][ni][2] + bb.x, acc[mi][ni][3] + bb.y);
            }
        }
    }
}

// ---------------- host launcher --------------------------------------------------
extern "C" void kernel_launch(void* const* d_in, const int* in_sizes, int n_in,
                              void* d_out, int out_size) {
    const float* hs = (const float*)d_in[0];
    const float* Wg = (const float*)d_in[3];
    const float* bg = (const float*)d_in[4];
    const float* W1 = (const float*)d_in[5];
    const float* b1 = (const float*)d_in[6];
    const float* W2 = (const float*)d_in[7];
    const float* b2 = (const float*)d_in[8];
    const void*  labels = d_in[9];

    void *pX, *pA, *pW1H, *pW2H;
    cudaGetSymbolAddress(&pX, g_X);
    cudaGetSymbolAddress(&pA, g_A);
    cudaGetSymbolAddress(&pW1H, g_W1H);
    cudaGetSymbolAddress(&pW2H, g_W2H);

    cudaFuncSetAttribute(hgemm_kernel<0, DFF, HDIM>,
                         cudaFuncAttributeMaxDynamicSharedMemorySize, SMEM_BYTES);
    cudaFuncSetAttribute(hgemm_kernel<1, HDIM, DFF>,
                         cudaFuncAttributeMaxDynamicSharedMemorySize, SMEM_BYTES);
    int n4 = HDIM * DFF / 4;

    // prep: W1 cast + labels-dtype detect + counter reset (one launch)
    prep_kernel<<<(n4 + 255) / 256, 256>>>(W1, (__half*)pW1H, n4, (const int*)labels);
    gate_kernel<<<TOK / 8, 256>>>(hs, Wg, bg, labels, (float*)d_out);
    // GEMM1: g_A = relu(Xc @ W1 + b1), fp16 (compact rows)
    hgemm_kernel<0, DFF, HDIM><<<dim3(DFF / BN, TOK / BM), NTHREADS, SMEM_BYTES>>>(
        (const __half*)pX, (const __half*)pW1H, b1, pA);
    cast_kernel<<<(n4 + 255) / 256, 256>>>(W2, (__half*)pW2H, n4);
    // GEMM2: d_out[rowmap] = Ac @ W2 + b2, fp32 scatter
    hgemm_kernel<1, HDIM, DFF><<<dim3(HDIM / BN, TOK / BM), NTHREADS, SMEM_BYTES>>>(
        (const __half*)pA, (const __half*)pW2H, b2, d_out);
}

// round 15
// speedup vs baseline: 1.1471x; 1.0061x over previous
#include <cuda_runtime.h>
#include <cuda_fp16.h>
#include <math.h>
#include <stdint.h>

#define TOK 16384
#define HDIM 1024
#define DFF  4096

// ---------------- scratch (static device globals; no allocation) ----------------
__device__ __align__(256) __half g_X  [(size_t)TOK * HDIM];   // compact xg fp16
__device__ __align__(256) __half g_A  [(size_t)TOK * DFF];    // compact relu intermediate
__device__ __align__(256) __half g_W1H[(size_t)HDIM * DFF];   // W1 fp16 [K,N]
__device__ __align__(256) __half g_W2H[(size_t)DFF * HDIM];   // W2 fp16 [K,N]
__device__ int g_rowmap[TOK];
__device__ int g_count;
__device__ int g_lab64;

// ---------------- kernel R: reset counter + labels-dtype detect (1 block) --------
__global__ void reset_kernel(const int* __restrict__ lab) {
    __shared__ int bad;
    if (threadIdx.x == 0) { bad = 0; g_count = 0; }
    __syncthreads();
    int local = 0;
    // int64 labels: (lo,hi) pairs with hi in {0,-1}, hi==-1 <=> lo==-100.
    for (int i = threadIdx.x; i < 2048; i += blockDim.x) {
        int lo = lab[2 * i], hi = lab[2 * i + 1];
        bool ok64 = (hi == 0 && lo >= 0) || (hi == -1 && lo == -100);
        if (!ok64) local = 1;
    }
    if (local) bad = 1;
    __syncthreads();
    if (threadIdx.x == 0) g_lab64 = bad ? 0 : 1;
}

// ---------------- kernel F: fused weight casts + gate (independent work) ---------
#define CAST_BLOCKS 8192                   // 2 * (HDIM*DFF/4) / 256
#define GATE_BLOCKS (TOK / 8)              // 2048

__global__ void aux_kernel(const float* __restrict__ W1, const float* __restrict__ W2,
                           const float* __restrict__ hs,
                           const float* __restrict__ Wg, const float* __restrict__ bg,
                           const void*  __restrict__ labels,
                           float* __restrict__ out) {
    const int n4 = HDIM * DFF / 4;
    if (blockIdx.x < CAST_BLOCKS) {
        int i = blockIdx.x * blockDim.x + threadIdx.x;
        const float4* src;
        uint2* dst;
        int j;
        if (i < n4) { src = (const float4*)W1; dst = (uint2*)g_W1H; j = i; }
        else        { src = (const float4*)W2; dst = (uint2*)g_W2H; j = i - n4; }
        float4 v = src[j];
        __half2 h0 = __floats2half2_rn(v.x, v.y);
        __half2 h1 = __floats2half2_rn(v.z, v.w);
        uint2 r;
        r.x = *(uint32_t*)&h0;
        r.y = *(uint32_t*)&h1;
        dst[j] = r;
        return;
    }
    // ---- gate blocks ----
    __shared__ float4 sWg[HDIM / 4];
    for (int i = threadIdx.x; i < HDIM / 4; i += blockDim.x)
        sWg[i] = ((const float4*)Wg)[i];
    __syncthreads();
    int warp = threadIdx.x >> 5, lane = threadIdx.x & 31;
    int t = (blockIdx.x - CAST_BLOCKS) * 8 + warp;
    const float4* hr = (const float4*)(hs + (size_t)t * HDIM);
    float4 v[8];
    float s = 0.f;
#pragma unroll
    for (int i = 0; i < 8; i++) {
        v[i] = hr[lane + 32 * i];
        float4 w4 = sWg[lane + 32 * i];
        s += v[i].x * w4.x + v[i].y * w4.y + v[i].z * w4.z + v[i].w * w4.w;
    }
#pragma unroll
    for (int o = 16; o; o >>= 1) s += __shfl_xor_sync(0xffffffffu, s, o);
    float logit = s + bg[0];
    float w = 1.f / (1.f + expf(-logit));
    long long lab;
    if (g_lab64) lab = ((const long long*)labels)[t];
    else         lab = (long long)(((const int*)labels)[t]);
    bool keep = (logit >= 0.f) || (lab == -100LL);
    int slot = -1;
    if (lane == 0 && keep) slot = atomicAdd(&g_count, 1);
    slot = __shfl_sync(0xffffffffu, slot, 0);
    if (keep) {
        if (lane == 0) g_rowmap[slot] = t;
        uint2* xr = (uint2*)(g_X + (size_t)slot * HDIM);
#pragma unroll
        for (int i = 0; i < 8; i++) {
            __half2 h0 = __floats2half2_rn(v[i].x * w, v[i].y * w);
            __half2 h1 = __floats2half2_rn(v[i].z * w, v[i].w * w);
            uint2 r;
            r.x = *(uint32_t*)&h0;
            r.y = *(uint32_t*)&h1;
            xr[lane + 32 * i] = r;
        }
    } else {
        float4 z = make_float4(0.f, 0.f, 0.f, 0.f);
        float4* orow = (float4*)(out + (size_t)t * HDIM);
#pragma unroll
        for (int i = 0; i < 8; i++) orow[lane + 32 * i] = z;
    }
}

// ---------------- GEMM: C[Mc,N] = A[Mc,K] * B[K,N]  (B native [K,N]) ------------
// CTA tile 128x128, 256 threads (8 warps, 4x2), warp tile 32x64, BK=64, 3 stages.
// Next-stage cp.async interleaved between kk-chunks. MODE/N/K compile-time.
#define BM 128
#define BN 128
#define BK 64
#define STAGES 3
#define NTHREADS 256
#define A_PITCH 144                       // (64+8) halves * 2B
#define B_PITCH 272                       // (128+8) halves * 2B
#define STAGE_A (BM * A_PITCH)            // 18432
#define STAGE_B (BK * B_PITCH)            // 17408
#define STAGE_BYTES (STAGE_A + STAGE_B)   // 35840
#define SMEM_BYTES (STAGES * STAGE_BYTES) // 107520

__device__ __forceinline__ uint32_t smem_u32(const void* p) {
    uint32_t a;
    asm("{ .reg .u64 t; cvta.to.shared.u64 t, %1; cvt.u32.u64 %0, t; }" : "=r"(a) : "l"(p));
    return a;
}
__device__ __forceinline__ void cp16s(uint32_t s, const void* g) {
    asm volatile("cp.async.cg.shared.global [%0], [%1], 16;\n" :: "r"(s), "l"(g));
}
__device__ __forceinline__ void cp16z(uint32_t s, const void* g, int valid) {
    int sz = valid ? 16 : 0;
    asm volatile("cp.async.cg.shared.global [%0], [%1], 16, %2;\n" :: "r"(s), "l"(g), "r"(sz));
}
__device__ __forceinline__ void cp_commit() { asm volatile("cp.async.commit_group;\n"); }
template <int N_> __device__ __forceinline__ void cp_wait() {
    asm volatile("cp.async.wait_group %0;\n" :: "n"(N_));
}
__device__ __forceinline__ void ldm_x4(uint32_t a, uint32_t& r0, uint32_t& r1,
                                       uint32_t& r2, uint32_t& r3) {
    asm volatile("ldmatrix.sync.aligned.m8n8.x4.shared.b16 {%0,%1,%2,%3}, [%4];"
                 : "=r"(r0), "=r"(r1), "=r"(r2), "=r"(r3) : "r"(a));
}
__device__ __forceinline__ void ldm_x4t(uint32_t a, uint32_t& r0, uint32_t& r1,
                                        uint32_t& r2, uint32_t& r3) {
    asm volatile("ldmatrix.sync.aligned.m8n8.x4.trans.shared.b16 {%0,%1,%2,%3}, [%4];"
                 : "=r"(r0), "=r"(r1), "=r"(r2), "=r"(r3) : "r"(a));
}

template <int K>
__device__ __forceinline__ void load_stage_A(uint32_t base,
                                             const __half* __restrict__ A,
                                             int bm, int k0, int tid, int Mc) {
#pragma unroll
    for (int i = 0; i < 4; i++) {
        int idx = tid + i * NTHREADS;
        int row = idx >> 3, cc = idx & 7;
        int gr = bm + row;
        cp16z(base + row * A_PITCH + cc * 16, A + (size_t)gr * K + k0 + cc * 8, gr < Mc);
    }
}
template <int N>
__device__ __forceinline__ void load_stage_B(uint32_t base,
                                             const __half* __restrict__ B,
                                             int bn, int k0, int tid) {
    uint32_t bb = base + STAGE_A;
#pragma unroll
    for (int i = 0; i < 4; i++) {
        int idx = tid + i * NTHREADS;
        int row = idx >> 4, cc = idx & 15;
        cp16s(bb + row * B_PITCH + cc * 16, B + (size_t)(k0 + row) * N + bn + cc * 8);
    }
}

// MODE 0: g_A[row] = relu(acc+bias) fp16 ; MODE 1: d_out[rowmap[row]] = acc+bias fp32
template <int MODE, int N, int K>
__global__ void __launch_bounds__(NTHREADS) hgemm_kernel(
    const __half* __restrict__ A, const __half* __restrict__ B,
    const float* __restrict__ bias, void* __restrict__ Cout)
{
    int Mc = *(volatile int*)&g_count;
    int bm = blockIdx.y * BM;
    if (bm >= Mc) return;
    int bn = blockIdx.x * BN;

    extern __shared__ char smraw[];
    uint32_t sb = smem_u32(smraw);
    int tid = threadIdx.x;
    int warp = tid >> 5, lane = tid & 31;
    int wm = warp & 3, wn = warp >> 2;             // 4x2 warps; warp tile 32x64

    float acc[2][8][4];
#pragma unroll
    for (int i = 0; i < 2; i++)
#pragma unroll
        for (int j = 0; j < 8; j++)
#pragma unroll
            for (int r = 0; r < 4; r++) acc[i][j][r] = 0.f;

    constexpr int kt = K / BK;
#pragma unroll
    for (int s = 0; s < STAGES - 1; s++) {
        load_stage_A<K>(sb + s * STAGE_BYTES, A, bm, s * BK, tid, Mc);
        load_stage_B<N>(sb + s * STAGE_BYTES, B, bn, s * BK, tid);
        cp_commit();
    }

    uint32_t a_lane = (uint32_t)(wm * 32 + (lane & 15)) * A_PITCH + (((lane >> 4) << 3) << 1);
    uint32_t b_lane = (uint32_t)((lane & 7) + (((lane >> 3) & 1) << 3)) * B_PITCH
                    + (((uint32_t)(wn * 64 + ((lane >> 4) << 3))) << 1);
    int g = lane >> 2, tq = lane & 3;

#pragma unroll 1
    for (int k = 0; k < kt; k++) {
        cp_wait<STAGES - 2>();
        __syncthreads();
        int kn = k + STAGES - 1;
        int do_load = kn < kt;
        uint32_t lbase = sb + (kn % STAGES) * STAGE_BYTES;
        int lk0 = kn * BK;
        uint32_t a_base = sb + (k % STAGES) * STAGE_BYTES + a_lane;
        uint32_t b_base = sb + (k % STAGES) * STAGE_BYTES + STAGE_A + b_lane;
#pragma unroll
        for (int kk = 0; kk < 4; kk++) {
            uint32_t afr[2][4], bfr[8][2];
#pragma unroll
            for (int mi = 0; mi < 2; mi++)
                ldm_x4(a_base + mi * (16 * A_PITCH) + kk * 32,
                       afr[mi][0], afr[mi][1], afr[mi][2], afr[mi][3]);
#pragma unroll
            for (int p = 0; p < 4; p++)
                ldm_x4t(b_base + kk * (16 * B_PITCH) + p * 32,
                        bfr[2 * p][0], bfr[2 * p][1], bfr[2 * p + 1][0], bfr[2 * p + 1][1]);
#pragma unroll
            for (int mi = 0; mi < 2; mi++)
#pragma unroll
                for (int ni = 0; ni < 8; ni++)
                    asm volatile(
                        "mma.sync.aligned.m16n8k16.row.col.f32.f16.f16.f32 "
                        "{%0,%1,%2,%3}, {%4,%5,%6,%7}, {%8,%9}, {%0,%1,%2,%3};\n"
                        : "+f"(acc[mi][ni][0]), "+f"(acc[mi][ni][1]),
                          "+f"(acc[mi][ni][2]), "+f"(acc[mi][ni][3])
                        : "r"(afr[mi][0]), "r"(afr[mi][1]),
                          "r"(afr[mi][2]), "r"(afr[mi][3]),
                          "r"(bfr[ni][0]), "r"(bfr[ni][1]));
            if (kk == 0 && do_load) load_stage_A<K>(lbase, A, bm, lk0, tid, Mc);
            if (kk == 1) {
                if (do_load) load_stage_B<N>(lbase, B, bn, lk0, tid);
                cp_commit();
            }
        }
    }

    int r0 = bm + wm * 32;
    int c0 = bn + wn * 64;
    if (MODE == 0) {
        __half* C = (__half*)Cout;
#pragma unroll
        for (int mi = 0; mi < 2; mi++) {
            int row = r0 + mi * 16 + g;
#pragma unroll
            for (int ni = 0; ni < 8; ni++) {
                int col = c0 + ni * 8 + tq * 2;
                float2 bb = *(const float2*)(bias + col);
                float v0 = fmaxf(acc[mi][ni][0] + bb.x, 0.f);
                float v1 = fmaxf(acc[mi][ni][1] + bb.y, 0.f);
                float v2 = fmaxf(acc[mi][ni][2] + bb.x, 0.f);
                float v3 = fmaxf(acc[mi][ni][3] + bb.y, 0.f);
                *(__half2*)(C + (size_t)row * N + col)       = __floats2half2_rn(v0, v1);
                *(__half2*)(C + (size_t)(row + 8) * N + col) = __floats2half2_rn(v2, v3);
            }
        }
    } else {
        float* C = (float*)Cout;
#pragma unroll
        for (int mi = 0; mi < 2; mi++) {
            int row = r0 + mi * 16 + g;
            int ok0 = row < Mc, ok1 = (row + 8) < Mc;
            size_t t0 = ok0 ? (size_t)g_rowmap[row] : 0;
            size_t t1 = ok1 ? (size_t)g_rowmap[row + 8] : 0;
#pragma unroll
            for (int ni = 0; ni < 8; ni++) {
                int col = c0 + ni * 8 + tq * 2;
                float2 bb = *(const float2*)(bias + col);
                if (ok0)
                    *(float2*)(C + t0 * N + col) =
                        make_float2(acc[mi][ni][0] + bb.x, acc[mi][ni][1] + bb.y);
                if (ok1)
                    *(float2*)(C + t1 * N + col) =
                        make_float2(acc[mi][ni][2] + bb.x, acc[mi][ni][3] + bb.y);
            }
        }
    }
}

// ---------------- host launcher --------------------------------------------------
extern "C" void kernel_launch(void* const* d_in, const int* in_sizes, int n_in,
                              void* d_out, int out_size) {
    const float* hs = (const float*)d_in[0];
    const float* Wg = (const float*)d_in[3];
    const float* bg = (const float*)d_in[4];
    const float* W1 = (const float*)d_in[5];
    const float* b1 = (const float*)d_in[6];
    const float* W2 = (const float*)d_in[7];
    const float* b2 = (const float*)d_in[8];
    const void*  labels = d_in[9];

    void *pX, *pA, *pW1H, *pW2H;
    cudaGetSymbolAddress(&pX, g_X);
    cudaGetSymbolAddress(&pA, g_A);
    cudaGetSymbolAddress(&pW1H, g_W1H);
    cudaGetSymbolAddress(&pW2H, g_W2H);

    cudaFuncSetAttribute(hgemm_kernel<0, DFF, HDIM>,
                         cudaFuncAttributeMaxDynamicSharedMemorySize, SMEM_BYTES);
    cudaFuncSetAttribute(hgemm_kernel<1, HDIM, DFF>,
                         cudaFuncAttributeMaxDynamicSharedMemorySize, SMEM_BYTES);

    // reset + labels-dtype detect (tiny)
    reset_kernel<<<1, 256>>>((const int*)labels);
    // fused: both weight casts + gate/compact/zero (independent, share the chip)
    aux_kernel<<<CAST_BLOCKS + GATE_BLOCKS, 256>>>(W1, W2, hs, Wg, bg, labels,
                                                   (float*)d_out);
    // GEMM1: g_A = relu(Xc @ W1 + b1), fp16 (compact rows)
    hgemm_kernel<0, DFF, HDIM><<<dim3(DFF / BN, TOK / BM), NTHREADS, SMEM_BYTES>>>(
        (const __half*)pX, (const __half*)pW1H, b1, pA);
    // GEMM2: d_out[rowmap] = Ac @ W2 + b2, fp32 scatter
    hgemm_kernel<1, HDIM, DFF><<<dim3(HDIM / BN, TOK / BM), NTHREADS, SMEM_BYTES>>>(
        (const __half*)pA, (const __half*)pW2H, b2, d_out);
}